// round 4
// baseline (speedup 1.0000x reference)
#include <cuda_runtime.h>

// Sinkhorn fixed-point for fermionic canonical partition functions.
// B=2048 systems, P=64 orbitals, N_PART=32. One warp per system, 2 orbitals/lane.
//
//  - Power sums C_k via 5-stage XOR-butterfly multi-reduction; packed f32x2
//    power generation (mul.rn.f32x2 halves the FMUL count).
//  - Nested Q-ratio recursion pipelined as a wavefront, fully unrolled,
//    with an UNPREDICATED per-step divide: every lane computes
//    iQ = (lane+1)/C1 * rcp(prev) every step; only the diagonal lane's value
//    is ever read by the broadcast, so no ISETP/predication is needed.
//  - Per-orbital aux scan fused into the same steps.
//  - Per-iteration normalization replaced by a 1-shuffle gauge fix
//    (the map is shift-equivariant); true normalization applied once at end.

#define FULLMASK 0xFFFFFFFFu
#define N_PART 32

__device__ __forceinline__ float warpSum(float v) {
    v += __shfl_xor_sync(FULLMASK, v, 16);
    v += __shfl_xor_sync(FULLMASK, v, 8);
    v += __shfl_xor_sync(FULLMASK, v, 4);
    v += __shfl_xor_sync(FULLMASK, v, 2);
    v += __shfl_xor_sync(FULLMASK, v, 1);
    return v;
}

__global__ void __launch_bounds__(128, 4) sinkhorn_kernel(
    const float* __restrict__ n_in,
    const float* __restrict__ beta_p,
    const int*   __restrict__ iters_p,
    float* __restrict__ out,
    int B)
{
    const int warpId = (blockIdx.x * blockDim.x + threadIdx.x) >> 5;
    if (warpId >= B) return;
    const int lane = threadIdx.x & 31;

    const float beta    = beta_p[0];
    const float invBeta = 1.0f / beta;
    const int   n_iters = iters_p[0];
    const float cExp = -beta * 1.442695040888963f;     // exp(-b*e) = exp2(cExp*e)
    const float cLog = -0.6931471805599453f * invBeta; // -log(t)/b = cLog*log2(t)

    // ---- load occupations, build nn and the GC guess ----
    const float* np = n_in + (size_t)warpId * 64;
    float n0 = np[lane];
    float n1 = np[lane + 32];
    float s  = warpSum(n0 + n1);
    float scale = 32.0f / s;
    float nn0 = n0 * scale, nn1 = n1 * scale;
    float r0 = __fdividef(nn0, 1.0f - nn0);   // nn/(1-nn), reused every iter
    float r1 = __fdividef(nn1, 1.0f - nn1);
    float eps0 = cLog * __log2f(r0);
    float eps1 = cLog * __log2f(r1);

    const float lanePlus1 = (float)(lane + 1);

    #pragma unroll 1
    for (int it = 0; it < n_iters; ++it) {
        // ---- phase 1: Boltzmann factors ----
        float x0 = exp2f(cExp * eps0);
        float x1 = exp2f(cExp * eps1);

        // ---- phase 2: packed power generation + butterfly multi-reduction.
        // After the butterfly, lane j holds C_{j+1}.
        float arr[N_PART];
        {
            unsigned long long x2, y2;
            asm("mov.b64 %0, {%1, %2};" : "=l"(x2) : "f"(x0), "f"(x1));
            y2 = x2;
            float lo, hi;
            asm("mov.b64 {%0, %1}, %2;" : "=f"(lo), "=f"(hi) : "l"(y2));
            arr[0] = lo + hi;
            #pragma unroll
            for (int k = 1; k < N_PART; ++k) {
                asm("mul.rn.f32x2 %0, %1, %2;" : "=l"(y2) : "l"(y2), "l"(x2));
                asm("mov.b64 {%0, %1}, %2;" : "=f"(lo), "=f"(hi) : "l"(y2));
                arr[k] = lo + hi;
            }
        }
        #pragma unroll
        for (int sft = 16; sft >= 1; sft >>= 1) {
            bool hi = (lane & sft) != 0;
            #pragma unroll
            for (int i = 0; i < sft; ++i) {
                float send = hi ? arr[i] : arr[i + sft];
                float keep = hi ? arr[i + sft] : arr[i];
                arr[i] = keep + __shfl_xor_sync(FULLMASK, send, sft);
            }
        }
        float W  = arr[0];                               // C[lane+1]
        float Wm = __shfl_up_sync(FULLMASK, W, 1);       // C[lane]
        if (lane == 0) Wm = 1.0f;
        float E  = __fdividef(W, Wm);                    // E[lane]
        float C1 = __shfl_sync(FULLMASK, W, 0);

        // ---- phase 3+4 fused, fully unrolled wavefront ----
        // lane j computes Q[j] (M=j+1). Step kk broadcasts iQ[kk-1] from lane
        // kk-1 (its value as of step kk-1). All updates are UNCONDITIONAL:
        // off-diagonal lanes produce garbage that is never read.
        float kOverC1 = __fdividef(lanePlus1, C1);       // (lane+1)/C1
        float iQ   = kOverC1;                            // lane 0: 1/Q[0]=1/C1
        float prev = 1.0f;
        float Es = E;
        float p0 = 1.0f, p1 = 1.0f;
        #pragma unroll
        for (int kk = 1; kk < N_PART; ++kk) {
            float iqb = __shfl_sync(FULLMASK, iQ, kk - 1);
            float t  = Es * prev;                         // off the serial chain
            float u0 = x0 * p0;
            float u1 = x1 * p1;
            prev = fmaf(-t,  iqb, 1.0f);
            p0   = fmaf(-u0, iqb, 1.0f);
            p1   = fmaf(-u1, iqb, 1.0f);
            iQ   = kOverC1 * __frcp_rz(prev) ;           // see note below
            Es   = __shfl_up_sync(FULLMASK, Es, 1);       // E[j - kk] next
        }
        // loop exit: p = ys[N-2]; final aux step k=31 uses iQ[31]
        float iq31  = __shfl_sync(FULLMASK, iQ, N_PART - 1);
        float Qp0_0 = p0 * iq31;                          // ys[N-2]/Q[N-1]
        float Qp0_1 = p1 * iq31;
        float v0 = x0 * p0, v1 = x1 * p1;
        p0 = fmaf(-v0, iq31, 1.0f);                       // ys[N-1] = Qp1
        p1 = fmaf(-v1, iq31, 1.0f);

        // ---- phase 5: update + gauge fix (shift-equivariant map) ----
        float e0 = cLog * __log2f(__fdividef(r0 * p0, Qp0_0));
        float e1 = cLog * __log2f(__fdividef(r1 * p1, Qp0_1));
        float g = __shfl_sync(FULLMASK, e0, 0);           // cheap gauge anchor
        eps0 = e0 - g;
        eps1 = e1 - g;
    }

    // ---- true normalization, once: sum_p nn_p eps_p = 0 ----
    float m = warpSum(nn0 * eps0 + nn1 * eps1) * (1.0f / 32.0f);
    out[(size_t)warpId * 64 + lane]      = eps0 - m;
    out[(size_t)warpId * 64 + lane + 32] = eps1 - m;
}

extern "C" void kernel_launch(void* const* d_in, const int* in_sizes, int n_in,
                              void* d_out, int out_size) {
    const float* n_ptr    = (const float*)d_in[0];
    const float* beta_ptr = (const float*)d_in[1];
    const int*   it_ptr   = (const int*)d_in[2];
    float* out = (float*)d_out;

    int B = in_sizes[0] / 64;           // systems; P=64 orbitals each
    int threads = 128;                  // 4 warps = 4 systems per block
    int blocks = (B * 32 + threads - 1) / threads;
    sinkhorn_kernel<<<blocks, threads>>>(n_ptr, beta_ptr, it_ptr, out, B);
}

// round 6
// speedup vs baseline: 1.3824x; 1.3824x over previous
#include <cuda_runtime.h>

// Sinkhorn fixed-point for fermionic canonical partition functions.
// B=2048 systems, P=64 orbitals, N_PART=32. One warp per system, 2 orbitals/lane.
//
//  - Power sums C_k via 5-stage XOR-butterfly multi-reduction (31 shuffles
//    for all 32 sums); lane j ends with C_{j+1}.
//  - Nested Q-ratio recursion pipelined as a wavefront, fully unrolled.
//    Unconditional per-step fast divide: every lane computes
//    iQ = (lane+1)/C1 * rcp(prev); only the diagonal lane's value is ever
//    read by the broadcast, so no predication is needed.
//  - Per-orbital aux scan fused into the same steps.
//  - Per-iteration normalization replaced by a 1-shuffle gauge fix
//    (the map is shift-equivariant); true normalization applied once at end.

#define FULLMASK 0xFFFFFFFFu
#define N_PART 32

__device__ __forceinline__ float warpSum(float v) {
    v += __shfl_xor_sync(FULLMASK, v, 16);
    v += __shfl_xor_sync(FULLMASK, v, 8);
    v += __shfl_xor_sync(FULLMASK, v, 4);
    v += __shfl_xor_sync(FULLMASK, v, 2);
    v += __shfl_xor_sync(FULLMASK, v, 1);
    return v;
}

__global__ void __launch_bounds__(128) sinkhorn_kernel(
    const float* __restrict__ n_in,
    const float* __restrict__ beta_p,
    const int*   __restrict__ iters_p,
    float* __restrict__ out,
    int B)
{
    const int warpId = (blockIdx.x * blockDim.x + threadIdx.x) >> 5;
    if (warpId >= B) return;
    const int lane = threadIdx.x & 31;

    const float beta    = beta_p[0];
    const float invBeta = 1.0f / beta;
    const int   n_iters = iters_p[0];

    // ---- load occupations, build nn and the GC guess ----
    const float* np = n_in + (size_t)warpId * 64;
    float n0 = np[lane];
    float n1 = np[lane + 32];
    float s  = warpSum(n0 + n1);
    float scale = 32.0f / s;
    float nn0 = n0 * scale, nn1 = n1 * scale;
    float r0 = __fdividef(nn0, 1.0f - nn0);   // nn/(1-nn), reused every iter
    float r1 = __fdividef(nn1, 1.0f - nn1);
    float eps0 = -__logf(r0) * invBeta;
    float eps1 = -__logf(r1) * invBeta;

    const float lanePlus1 = (float)(lane + 1);

    #pragma unroll 1
    for (int it = 0; it < n_iters; ++it) {
        // ---- phase 1: Boltzmann factors ----
        float x0 = __expf(-beta * eps0);
        float x1 = __expf(-beta * eps1);

        // ---- phase 2: local power sums + butterfly multi-reduction.
        // After the butterfly, lane j holds C_{j+1}.
        float arr[N_PART];
        {
            float y0 = x0, y1 = x1;
            arr[0] = y0 + y1;
            #pragma unroll
            for (int k = 1; k < N_PART; ++k) {
                y0 *= x0; y1 *= x1;
                arr[k] = y0 + y1;
            }
        }
        #pragma unroll
        for (int sft = 16; sft >= 1; sft >>= 1) {
            bool hi = (lane & sft) != 0;
            #pragma unroll
            for (int i = 0; i < sft; ++i) {
                float send = hi ? arr[i] : arr[i + sft];
                float keep = hi ? arr[i + sft] : arr[i];
                arr[i] = keep + __shfl_xor_sync(FULLMASK, send, sft);
            }
        }
        float W  = arr[0];                               // C[lane+1]
        float Wm = __shfl_up_sync(FULLMASK, W, 1);       // C[lane]
        if (lane == 0) Wm = 1.0f;
        float E  = __fdividef(W, Wm);                    // E[lane]
        float C1 = __shfl_sync(FULLMASK, W, 0);

        // ---- phase 3+4 fused, fully unrolled wavefront ----
        // lane j computes Q[j] (M=j+1). Step kk broadcasts iQ[kk-1] from
        // lane kk-1 (its value as of step kk-1). All updates UNCONDITIONAL:
        // off-diagonal lanes produce garbage that is never read.
        float kOverC1 = __fdividef(lanePlus1, C1);       // (lane+1)/C1
        float iQ   = kOverC1;                            // lane 0: 1/Q[0]=1/C1
        float prev = 1.0f;
        float Es = E;
        float p0 = 1.0f, p1 = 1.0f;
        #pragma unroll
        for (int kk = 1; kk < N_PART; ++kk) {
            float iqb = __shfl_sync(FULLMASK, iQ, kk - 1);
            float t  = Es * prev;                         // off the serial chain
            float u0 = x0 * p0;
            float u1 = x1 * p1;
            prev = fmaf(-t,  iqb, 1.0f);
            p0   = fmaf(-u0, iqb, 1.0f);
            p1   = fmaf(-u1, iqb, 1.0f);
            iQ   = __fdividef(kOverC1, prev);             // MUFU.RCP + FMUL
            Es   = __shfl_up_sync(FULLMASK, Es, 1);       // E[j - kk] next
        }
        // loop exit: p = ys[N-2]; final aux step k=31 uses iQ[31]
        float iq31  = __shfl_sync(FULLMASK, iQ, N_PART - 1);
        float Qp0_0 = p0 * iq31;                          // ys[N-2]/Q[N-1]
        float Qp0_1 = p1 * iq31;
        float v0 = x0 * p0, v1 = x1 * p1;
        p0 = fmaf(-v0, iq31, 1.0f);                       // ys[N-1] = Qp1
        p1 = fmaf(-v1, iq31, 1.0f);

        // ---- phase 5: update + gauge fix (map is shift-equivariant) ----
        float e0 = -__logf(__fdividef(r0 * p0, Qp0_0)) * invBeta;
        float e1 = -__logf(__fdividef(r1 * p1, Qp0_1)) * invBeta;
        float g = __shfl_sync(FULLMASK, e0, 0);           // cheap gauge anchor
        eps0 = e0 - g;
        eps1 = e1 - g;
    }

    // ---- true normalization, once: sum_p nn_p eps_p = 0 ----
    float m = warpSum(nn0 * eps0 + nn1 * eps1) * (1.0f / 32.0f);
    out[(size_t)warpId * 64 + lane]      = eps0 - m;
    out[(size_t)warpId * 64 + lane + 32] = eps1 - m;
}

extern "C" void kernel_launch(void* const* d_in, const int* in_sizes, int n_in,
                              void* d_out, int out_size) {
    const float* n_ptr    = (const float*)d_in[0];
    const float* beta_ptr = (const float*)d_in[1];
    const int*   it_ptr   = (const int*)d_in[2];
    float* out = (float*)d_out;

    int B = in_sizes[0] / 64;           // systems; P=64 orbitals each
    int threads = 128;                  // 4 warps = 4 systems per block
    int blocks = (B * 32 + threads - 1) / threads;
    sinkhorn_kernel<<<blocks, threads>>>(n_ptr, beta_ptr, it_ptr, out, B);
}